// round 15
// baseline (speedup 1.0000x reference)
#include <cuda_runtime.h>
#include <cuda_fp16.h>
#include <math.h>

#define BB 64
#define TT 32
#define EE 300
#define HH 1024
#define VV 10000

#define E_PAD 384
#define NT1 44                        // k-tiles layer 1 (384+1024)/32
#define NTILE0_1 12
#define NT2 64                        // (1024+1024)/32
#define NTILE0_2 32
#define NBLK 64                       // blocks per layer, 64 gate-cols each

#define IMG_TILE_WORDS 1024           // one A or W tile image (4KB, fp16x2 words)
#define STAGE_BYTES 8192              // A tile + W tile
#define HALF_RING_STAGES 12           // 6 pair-steps in flight per half
#define HALF_RING_BYTES (HALF_RING_STAGES * STAGE_BYTES)   // 98304
#define SMEM_DYN (2 * HALF_RING_BYTES)                      // 196608

#define NTHREADS 512
#define NCTAS (2 * NBLK)              // 128
#define GSTRIDE (NCTAS * NTHREADS)    // 65536

// ---- persistent device scratch (no allocation allowed) ----
__device__ unsigned g_w1img[NBLK * NT1 * IMG_TILE_WORDS];   // 44 iters/thread
__device__ unsigned g_w2img[NBLK * NT2 * IMG_TILE_WORDS];   // 64 iters/thread
__device__ unsigned g_ximg[TT * NTILE0_1 * IMG_TILE_WORDS]; // 6 iters/thread
__device__ unsigned g_h1img[2][32 * IMG_TILE_WORDS];
__device__ unsigned g_h2img[2][32 * IMG_TILE_WORDS];
__device__ float g_h1[2][BB * HH];
__device__ float g_h2[2][BB * HH];
__device__ float g_c1[BB * HH];
__device__ float g_c2[BB * HH];
__device__ float g_bc1[4 * HH];
__device__ float g_bc2[4 * HH];
__device__ unsigned g_cnt1[TT];       // L1 phase-completion counters
__device__ unsigned g_cnt2[TT];       // L2 phase-completion counters
__device__ unsigned g_cntp;           // prep-done barrier
__device__ unsigned g_cnte;           // end barrier (for counter reset)

__device__ __forceinline__ unsigned pack_h2(float lo, float hi) {
    return (unsigned)__half_as_ushort(__float2half_rn(lo))
         | ((unsigned)__half_as_ushort(__float2half_rn(hi)) << 16);
}

__device__ __forceinline__ void cp16(unsigned dst, const void* src) {
    asm volatile("cp.async.cg.shared.global [%0], [%1], 16;"
                 :: "r"(dst), "l"(src));
}

__device__ __forceinline__ unsigned ld_acq(const unsigned* p) {
    unsigned v;
    asm volatile("ld.acquire.gpu.global.b32 %0, [%1];" : "=r"(v) : "l"(p));
    return v;
}

__device__ __forceinline__ float sigm_f(float x) {
    return 1.f / (1.f + __expf(-x));          // inf-safe both tails
}
__device__ __forceinline__ float tanh_f(float x) {
    return 1.f - 2.f / (__expf(2.f * x) + 1.f);  // inf-safe both tails
}

#define LDS128(r0,r1,r2,r3,addr) \
    asm volatile("ld.shared.v4.b32 {%0,%1,%2,%3}, [%4];" \
                 : "=r"(r0),"=r"(r1),"=r"(r2),"=r"(r3) : "r"(addr))

// fp16 image word layout, per 32-k tile (1024 fp16x2 words):
//   [half(2)][kstep(2)][lane l(32)][8]   — half = wm (A) or wn (W)
//   physical word w holds logical idx8 = w ^ (l & 4)   (anti-conflict swap)
//   A: idx8 = mb*4 + khalf*2 + rsel ->
//        A(row = 32*half + 16*mb + 8*rsel + (l>>2),
//          k pair = tile*32 + kstep*16 + khalf*8 + 2*(l&3))
//   W: idx8 = j*2 + khalf ->
//        W(gate j, unit = nb*16 + half*8 + (l>>2), same k pair)
__device__ __forceinline__ void w_img_word(unsigned* dst, int e,
    const float* __restrict__ Wih, const float* __restrict__ Whh,
    int Kin, int Kpad, int NT)
{
    int d = e & 1023;
    int nbtile = e >> 10;
    int tile = nbtile % NT;
    int nb = nbtile / NT;
    int half = d >> 9;
    int kstep = (d >> 8) & 1;
    int l = (d >> 3) & 31;
    int idx8 = (d & 7) ^ (l & 4);
    int j = idx8 >> 1, khalf = idx8 & 1;
    int g = l >> 2, th = l & 3;
    int r = j * HH + nb * 16 + half * 8 + g;
    int k = tile * 32 + kstep * 16 + khalf * 8 + 2 * th;
    float lo, hi;
    if (k < Kpad) {
        lo = (k < Kin)     ? Wih[(size_t)r * Kin + k] : 0.f;
        hi = (k + 1 < Kin) ? Wih[(size_t)r * Kin + k + 1] : 0.f;
    } else {
        lo = Whh[(size_t)r * HH + (k - Kpad)];
        hi = Whh[(size_t)r * HH + (k - Kpad) + 1];
    }
    dst[e] = pack_h2(lo, hi);
}

// Persistent fused kernel: prep phase (-1) + 64 pipelined LSTM layer-steps.
// 128 co-resident CTAs (1/SM). Blocks [0,64) = L2-role, [64,128) = L1-role.
//   L1 phase t waits cnt1[t-1]=64 and cnt2[t-2]=64 (ping-pong back-pressure).
//   L2 phase t waits cnt1[t]=64 and cnt2[t-1]=64.
// W images / x images are epoch-independent -> prefetched DURING the epoch
// spin; only h-image (A) loads are gated. 6-pair cp.async ring per half-block,
// named barriers, fragment-packed fp16 images, m16n8k16 f32-accum MMA,
// 4-way k-partials reduced through ring smem, thread-local LSTM epilogue.
__global__ __launch_bounds__(NTHREADS, 1) void lstm_persist(
    const int* __restrict__ questions,
    const int* __restrict__ qlen,
    const float* __restrict__ embed,
    const float* __restrict__ Wih1, const float* __restrict__ Whh1,
    const float* __restrict__ bih1, const float* __restrict__ bhh1,
    const float* __restrict__ Wih2, const float* __restrict__ Whh2,
    const float* __restrict__ bih2, const float* __restrict__ bhh2)
{
    extern __shared__ __align__(16) float sm[];
    const int tid   = threadIdx.x;
    const int lane  = tid & 31;
    const int warp  = tid >> 5;
    const int half  = warp >> 3;      // 0 or 1
    const int w8    = warp & 7;
    const int h_tid = tid & 255;

    // ================= phase -1: build all images (whole grid) =============
    {
        const int gtid = blockIdx.x * NTHREADS + tid;
#pragma unroll 4
        for (int i = gtid; i < NBLK * NT1 * IMG_TILE_WORDS; i += GSTRIDE)
            w_img_word(g_w1img, i, Wih1, Whh1, EE, E_PAD, NT1);
#pragma unroll 4
        for (int i = gtid; i < NBLK * NT2 * IMG_TILE_WORDS; i += GSTRIDE)
            w_img_word(g_w2img, i, Wih2, Whh2, HH, HH, NT2);
#pragma unroll 2
        for (int i = gtid; i < TT * NTILE0_1 * IMG_TILE_WORDS; i += GSTRIDE) {
            int d = i & 1023;
            int ttile = i >> 10;
            int tile = ttile % NTILE0_1;
            int t = ttile / NTILE0_1;
            int hl = d >> 9;
            int kstep = (d >> 8) & 1;
            int l = (d >> 3) & 31;
            int idx8 = (d & 7) ^ (l & 4);
            int mb = idx8 >> 2, khalf = (idx8 >> 1) & 1, rsel = idx8 & 1;
            int g = l >> 2, th = l & 3;
            int b = 32 * hl + 16 * mb + 8 * rsel + g;
            int k = tile * 32 + kstep * 16 + khalf * 8 + 2 * th;
            int row = questions[b * TT + t];
            float lo = (k < EE)     ? embed[(size_t)row * EE + k] : 0.f;
            float hi = (k + 1 < EE) ? embed[(size_t)row * EE + k + 1] : 0.f;
            g_ximg[i] = pack_h2(lo, hi);
        }
        if (gtid < 4 * HH) {
            g_bc1[gtid] = bih1[gtid] + bhh1[gtid];
            g_bc2[gtid] = bih2[gtid] + bhh2[gtid];
        }
        // zero states + h-images[0]: 4*65536 floats + 2*32768 words = 5 iters
        for (int i = gtid; i < 327680; i += GSTRIDE) {
            if (i < 262144) {
                int sec = i >> 16, off = i & 65535;
                if      (sec == 0) g_h1[0][off] = 0.f;
                else if (sec == 1) g_h2[0][off] = 0.f;
                else if (sec == 2) g_c1[off] = 0.f;
                else               g_c2[off] = 0.f;
            } else {
                int j = i - 262144;
                if (j < 32768) g_h1img[0][j] = 0u;
                else           g_h2img[0][j - 32768] = 0u;
            }
        }
        __threadfence();
        __syncthreads();
        if (tid == 0) {
            atomicAdd(&g_cntp, 1u);
            while (ld_acq(&g_cntp) < NCTAS) __nanosleep(40);
        }
        __syncthreads();
    }

    // ================= phases 0..31 ========================================
    const bool isL2 = blockIdx.x < NBLK;
    const int nb = blockIdx.x & (NBLK - 1);

    const int NT     = isL2 ? NT2 : NT1;
    const int ntile0 = isL2 ? NTILE0_2 : NTILE0_1;
    const int nsteps = NT >> 2;          // 11 or 16
    const unsigned* Wb = (isL2 ? g_w2img : g_w1img)
                       + (size_t)nb * NT * IMG_TILE_WORDS;
    const float* bc  = isL2 ? g_bc2 : g_bc1;
    float* cb        = isL2 ? g_c2 : g_c1;

    const unsigned smb = (unsigned)__cvta_generic_to_shared(sm)
                       + (unsigned)(half * HALF_RING_BYTES);

    const int wk2 = w8 & 1;
    const int wm  = (w8 >> 1) & 1;
    const int wn  = (w8 >> 2) & 1;
    const int g   = lane >> 2;
    const int th  = lane & 3;
    const unsigned lbase = (unsigned)(lane * 32) + ((lane & 4) ? 16u : 0u);
    const int barid = half + 1;
    const int kslot = half * 2 + wk2;

    // constant part of the h-image scatter address
    const int scat_base = (nb >> 1) * 1024 + wm * 512 + (nb & 1) * 256 + lane * 8;

    for (int t = 0; t < TT; ++t) {
        // ---- per-phase pointers (computable before the epoch wait) ----
        const unsigned *A0img, *A1img;
        const float *hprev;
        float *ho;
        unsigned *hoimg;
        if (isL2) {
            A0img = g_h1img[(t + 1) & 1];
            A1img = g_h2img[t & 1];
            hprev = g_h2[t & 1];
            ho    = g_h2[(t + 1) & 1];
            hoimg = g_h2img[(t + 1) & 1];
        } else {
            A0img = g_ximg + (size_t)t * (NTILE0_1 * IMG_TILE_WORDS);
            A1img = g_h1img[t & 1];
            hprev = g_h1[t & 1];
            ho    = g_h1[(t + 1) & 1];
            hoimg = g_h1img[(t + 1) & 1];
        }

        auto issue_W = [&](int s) {
            int st = (s % 6) * 2;
            int tb = 4 * s + 2 * half;
#pragma unroll
            for (int q = 0; q < 2; ++q) {
                const unsigned* wsrc = Wb + (size_t)(tb + q) * IMG_TILE_WORDS;
                unsigned ab = smb + (unsigned)((st + q) * STAGE_BYTES);
                cp16(ab + 4096u + (unsigned)(h_tid * 16), (const uint4*)wsrc + h_tid);
            }
        };
        auto issue_A = [&](int s) {
            int st = (s % 6) * 2;
            int tb = 4 * s + 2 * half;
#pragma unroll
            for (int q = 0; q < 2; ++q) {
                int tt = tb + q;
                const unsigned* asrc = (tt < ntile0)
                    ? A0img + (size_t)tt * IMG_TILE_WORDS
                    : A1img + (size_t)(tt - ntile0) * IMG_TILE_WORDS;
                unsigned ab = smb + (unsigned)((st + q) * STAGE_BYTES);
                cp16(ab + (unsigned)(h_tid * 16), (const uint4*)asrc + h_tid);
            }
        };

        // ---- prefetch epoch-independent tiles, then epoch wait ----
        issue_W(0); issue_W(1); issue_W(2); issue_W(3); issue_W(4);
        if (!isL2) { issue_A(0); issue_A(1); issue_A(2); }  // x tiles: all < ntile0

        if (tid == 0) {
            if (isL2) {
                while (ld_acq(&g_cnt1[t]) < NBLK) __nanosleep(40);
                if (t > 0) while (ld_acq(&g_cnt2[t - 1]) < NBLK) __nanosleep(40);
            } else {
                if (t > 0)  while (ld_acq(&g_cnt1[t - 1]) < NBLK) __nanosleep(40);
                if (t >= 2) while (ld_acq(&g_cnt2[t - 2]) < NBLK) __nanosleep(40);
            }
        }
        __syncthreads();

        // ---- commit prologue groups (A parts now unblocked) ----
        if (isL2) issue_A(0);
        asm volatile("cp.async.commit_group;");
        if (isL2) issue_A(1);
        asm volatile("cp.async.commit_group;");
        if (isL2) issue_A(2);
        asm volatile("cp.async.commit_group;");
        issue_A(3);
        asm volatile("cp.async.commit_group;");
        issue_A(4);
        asm volatile("cp.async.commit_group;");

        float acc[32];
#pragma unroll
        for (int i = 0; i < 32; ++i) acc[i] = 0.f;

        for (int s = 0; s < nsteps; ++s) {
            asm volatile("cp.async.wait_group 4;");
            asm volatile("bar.sync %0, 256;" :: "r"(barid));
            if (s + 5 < nsteps) { issue_A(s + 5); issue_W(s + 5); }
            asm volatile("cp.async.commit_group;");

            const unsigned st = smb + (unsigned)(((s % 6) * 2 + wk2) * STAGE_BYTES);
            const unsigned Ab  = st + (unsigned)(wm * 2048) + lbase;
            const unsigned Wsb = st + 4096u + (unsigned)(wn * 2048) + lbase;

#pragma unroll
            for (int c = 0; c < 2; ++c) {      // kstep of 16
                unsigned x0,x1,x2,x3,x4,x5,x6,x7;   // A logical idx8 0..7
                unsigned w0,w1,w2,w3,w4,w5,w6,w7;   // W logical idx8 0..7
                unsigned aaddr = Ab + (unsigned)(c * 1024);
                LDS128(x0, x1, x2, x3, aaddr);
                LDS128(x4, x5, x6, x7, aaddr ^ 16u);
                unsigned waddr = Wsb + (unsigned)(c * 1024);
                LDS128(w0, w1, w2, w3, waddr);
                LDS128(w4, w5, w6, w7, waddr ^ 16u);

#define MMAH(accp, A0_, A1_, A2_, A3_, B0_, B1_) \
    asm volatile("mma.sync.aligned.m16n8k16.row.col.f32.f16.f16.f32 " \
        "{%0,%1,%2,%3}, {%4,%5,%6,%7}, {%8,%9}, {%0,%1,%2,%3};" \
        : "+f"((accp)[0]), "+f"((accp)[1]), "+f"((accp)[2]), "+f"((accp)[3]) \
        : "r"(A0_), "r"(A1_), "r"(A2_), "r"(A3_), "r"(B0_), "r"(B1_))

                MMAH(&acc[0*8 + 0], x0, x1, x2, x3, w0, w1);  // j0 mb0
                MMAH(&acc[1*8 + 0], x0, x1, x2, x3, w2, w3);  // j1 mb0
                MMAH(&acc[2*8 + 0], x0, x1, x2, x3, w4, w5);  // j2 mb0
                MMAH(&acc[3*8 + 0], x0, x1, x2, x3, w6, w7);  // j3 mb0
                MMAH(&acc[0*8 + 4], x4, x5, x6, x7, w0, w1);  // j0 mb1
                MMAH(&acc[1*8 + 4], x4, x5, x6, x7, w2, w3);
                MMAH(&acc[2*8 + 4], x4, x5, x6, x7, w4, w5);
                MMAH(&acc[3*8 + 4], x4, x5, x6, x7, w6, w7);
#undef MMAH
            }
        }

        // ---- drain both half-rings, 4-way k-reduce via smem reuse ----
        asm volatile("cp.async.wait_group 0;");
        __syncthreads();

        if (kslot != 0) {
            int slot = (kslot - 1) * 4 + wm * 2 + wn;   // 0..11
            float4* dst = (float4*)(sm + slot * 1152 + lane * 36);
#pragma unroll
            for (int i = 0; i < 8; ++i)
                dst[i] = make_float4(acc[4*i], acc[4*i+1], acc[4*i+2], acc[4*i+3]);
        }
        __syncthreads();

        if (kslot == 0) {
#pragma unroll
            for (int kk = 1; kk < 4; ++kk) {
                const float4* src = (const float4*)(sm + ((kk - 1) * 4 + wm * 2 + wn) * 1152 + lane * 36);
#pragma unroll
                for (int i = 0; i < 8; ++i) {
                    float4 v = src[i];
                    acc[4*i]   += v.x; acc[4*i+1] += v.y;
                    acc[4*i+2] += v.z; acc[4*i+3] += v.w;
                }
            }

            // ---- thread-local LSTM epilogue ----
            // acc[j*8 + mb*4 + rsel*2 + e]:
            //   b = wm*32 + mb*16 + rsel*8 + g, u = nb*16 + wn*8 + 2*th + e
#pragma unroll
            for (int mb = 0; mb < 2; ++mb)
#pragma unroll
                for (int rsel = 0; rsel < 2; ++rsel) {
                    int b = wm * 32 + mb * 16 + rsel * 8 + g;
                    bool active = (t < qlen[b]);
                    float hw2[2];
#pragma unroll
                    for (int e = 0; e < 2; ++e) {
                        int u = nb * 16 + wn * 8 + 2 * th + e;
                        int ai = mb * 4 + rsel * 2 + e;
                        float gi = acc[0*8 + ai] + bc[u];
                        float gf = acc[1*8 + ai] + bc[u + HH];
                        float gg = acc[2*8 + ai] + bc[u + 2*HH];
                        float go = acc[3*8 + ai] + bc[u + 3*HH];
                        int idx = b * HH + u;
                        float c_old = cb[idx];
                        float h_old = hprev[idx];
                        float si = sigm_f(gi);
                        float sf = sigm_f(gf);
                        float so = sigm_f(go);
                        float tg = tanh_f(gg);
                        float cn = sf * c_old + si * tg;
                        float hn = so * tanh_f(cn);
                        float cw = active ? cn : c_old;
                        float hw = active ? hn : h_old;
                        cb[idx] = cw;
                        ho[idx] = hw;
                        hw2[e] = hw;
                    }
                    // one fp16x2 word into next-step A-image
                    int phys = (mb * 4 + wn * 2 + rsel) ^ (lane & 4);
                    hoimg[scat_base + phys] = pack_h2(hw2[0], hw2[1]);
                }
            __threadfence();   // publish h/c before epoch arrive
        }
        __syncthreads();       // all warps past reduction-smem reads

        if (tid == 0) {
            __threadfence();
            atomicAdd(isL2 ? &g_cnt2[t] : &g_cnt1[t], 1u);
        }
    }

    // ---- end barrier: block 0 resets all counters for the next replay ----
    if (tid == 0) {
        atomicAdd(&g_cnte, 1u);
        if (blockIdx.x == 0) {
            while (ld_acq(&g_cnte) < NCTAS) __nanosleep(40);
#pragma unroll
            for (int i = 0; i < TT; ++i) { g_cnt1[i] = 0u; g_cnt2[i] = 0u; }
            g_cntp = 0u;
            g_cnte = 0u;
        }
    }
}

// Output: E_q [B,1024,28,28] = tiled h2, then h1, h2, c1, c2 each [B,1,H].
__global__ void write_output_kernel(
    float* __restrict__ out,
    const float* __restrict__ h1,
    const float* __restrict__ h2,
    const float* __restrict__ c1,
    const float* __restrict__ c2)
{
    const unsigned n0q = (unsigned)BB * HH * 784u / 4u;
    const unsigned sq  = (unsigned)BB * HH / 4u;
    unsigned idx = blockIdx.x * blockDim.x + threadIdx.x;
    unsigned totq = n0q + 4u * sq;
    if (idx >= totq) return;
    float4* out4 = (float4*)out;
    if (idx < n0q) {
        unsigned bh = idx / 196u;
        float v = h2[bh];
        out4[idx] = make_float4(v, v, v, v);
    } else {
        unsigned r = idx - n0q;
        unsigned sec = r / sq;
        unsigned off = r % sq;
        const float* src = (sec == 0) ? h1 : (sec == 1) ? h2 : (sec == 2) ? c1 : c2;
        out4[idx] = ((const float4*)src)[off];
    }
}

extern "C" void kernel_launch(void* const* d_in, const int* in_sizes, int n_in,
                              void* d_out, int out_size) {
    const int*   questions = (const int*)d_in[0];
    const int*   qlen      = (const int*)d_in[1];
    const float* embed     = (const float*)d_in[2];
    const float* Wih1      = (const float*)d_in[3];
    const float* Whh1      = (const float*)d_in[4];
    const float* bih1      = (const float*)d_in[5];
    const float* bhh1      = (const float*)d_in[6];
    const float* Wih2      = (const float*)d_in[7];
    const float* Whh2      = (const float*)d_in[8];
    const float* bih2      = (const float*)d_in[9];
    const float* bhh2      = (const float*)d_in[10];

    void* p;
    cudaGetSymbolAddress(&p, g_h1); float (*h1b)[BB*HH] = (float(*)[BB*HH])p;
    cudaGetSymbolAddress(&p, g_h2); float (*h2b)[BB*HH] = (float(*)[BB*HH])p;
    cudaGetSymbolAddress(&p, g_c1); float* c1p = (float*)p;
    cudaGetSymbolAddress(&p, g_c2); float* c2p = (float*)p;

    cudaFuncSetAttribute(lstm_persist,
                         cudaFuncAttributeMaxDynamicSharedMemorySize, SMEM_DYN);

    // one persistent kernel: image build (phase -1) + all 64 layer-steps
    lstm_persist<<<NCTAS, NTHREADS, SMEM_DYN>>>(
        questions, qlen, embed, Wih1, Whh1, bih1, bhh1,
        Wih2, Whh2, bih2, bhh2);

    // final states live in buffer index (T % 2) == 0
    unsigned totq = (unsigned)BB * HH * 784u / 4u + (unsigned)BB * HH;
    write_output_kernel<<<(totq + 255) / 256, 256>>>(
        (float*)d_out, h1b[0], h2b[0], c1p, c2p);
}

// round 17
// speedup vs baseline: 1.0487x; 1.0487x over previous
#include <cuda_runtime.h>
#include <cuda_fp16.h>
#include <math.h>

#define BB 64
#define TT 32
#define EE 300
#define HH 1024
#define VV 10000

#define E_PAD 384
#define NT1 44                        // k-tiles layer 1 (384+1024)/32
#define NTILE0_1 12
#define NT2 64                        // (1024+1024)/32
#define NTILE0_2 32
#define NBLK 64                       // blocks per layer, 64 gate-cols each

#define IMG_TILE_WORDS 1024           // one A or W tile image (4KB, fp16x2 words)
#define STAGE_BYTES 8192              // A tile + W tile
#define HALF_RING_STAGES 12           // 6 pair-steps in flight per half
#define HALF_RING_BYTES (HALF_RING_STAGES * STAGE_BYTES)   // 98304
#define SMEM_DYN (2 * HALF_RING_BYTES)                      // 196608

#define NTHREADS 512
#define NCTAS (2 * NBLK)              // 128

// prep_all grid sections (256 threads each, exact word counts)
#define PW1 11264                     // 64*44*1024/256
#define PW2 (PW1 + 16384)             // + 64*64*1024/256
#define PX  (PW2 + 1536)              // + 32*12*1024/256
#define PBI (PX + 16)                 // + 4096/256
#define PZ  (PBI + 1280)              // + (4*65536 + 2*32768)/256
#define PEND (PZ + 1)                 // + counters

// ---- persistent device scratch (no allocation allowed) ----
__device__ unsigned g_w1img[NBLK * NT1 * IMG_TILE_WORDS];
__device__ unsigned g_w2img[NBLK * NT2 * IMG_TILE_WORDS];
__device__ unsigned g_ximg[TT * NTILE0_1 * IMG_TILE_WORDS];
__device__ unsigned g_h1img[2][32 * IMG_TILE_WORDS];
__device__ unsigned g_h2img[2][32 * IMG_TILE_WORDS];
__device__ float g_h1[2][BB * HH];
__device__ float g_h2[2][BB * HH];
__device__ float g_c1[BB * HH];
__device__ float g_c2[BB * HH];
__device__ float g_bc1[4 * HH];
__device__ float g_bc2[4 * HH];
__device__ unsigned g_cnt1[TT];       // L1 phase-completion counters
__device__ unsigned g_cnt2[TT];       // L2 phase-completion counters

__device__ __forceinline__ unsigned pack_h2(float lo, float hi) {
    return (unsigned)__half_as_ushort(__float2half_rn(lo))
         | ((unsigned)__half_as_ushort(__float2half_rn(hi)) << 16);
}

__device__ __forceinline__ void cp16(unsigned dst, const void* src) {
    asm volatile("cp.async.cg.shared.global [%0], [%1], 16;"
                 :: "r"(dst), "l"(src));
}

__device__ __forceinline__ unsigned ld_acq(const unsigned* p) {
    unsigned v;
    asm volatile("ld.acquire.gpu.global.b32 %0, [%1];" : "=r"(v) : "l"(p));
    return v;
}

__device__ __forceinline__ float sigm_f(float x) {
    return 1.f / (1.f + __expf(-x));          // inf-safe both tails
}
__device__ __forceinline__ float tanh_f(float x) {
    return 1.f - 2.f / (__expf(2.f * x) + 1.f);  // inf-safe both tails
}

#define LDS128(r0,r1,r2,r3,addr) \
    asm volatile("ld.shared.v4.b32 {%0,%1,%2,%3}, [%4];" \
                 : "=r"(r0),"=r"(r1),"=r"(r2),"=r"(r3) : "r"(addr))

// fp16 image word layout, per 32-k tile (1024 fp16x2 words):
//   [half(2)][kstep(2)][lane l(32)][8]   — half = wm (A) or wn (W)
//   physical word w holds logical idx8 = w ^ (l & 4)   (anti-conflict swap)
//   A: idx8 = mb*4 + khalf*2 + rsel ->
//        A(row = 32*half + 16*mb + 8*rsel + (l>>2),
//          k pair = tile*32 + kstep*16 + khalf*8 + 2*(l&3))
//   W: idx8 = j*2 + khalf ->
//        W(gate j, unit = nb*16 + half*8 + (l>>2), same k pair)
__device__ __forceinline__ void w_img_word(unsigned* dst, int e,
    const float* __restrict__ Wih, const float* __restrict__ Whh,
    int Kin, int Kpad, int NT)
{
    int d = e & 1023;
    int nbtile = e >> 10;
    int tile = nbtile % NT;
    int nb = nbtile / NT;
    int half = d >> 9;
    int kstep = (d >> 8) & 1;
    int l = (d >> 3) & 31;
    int idx8 = (d & 7) ^ (l & 4);
    int j = idx8 >> 1, khalf = idx8 & 1;
    int g = l >> 2, th = l & 3;
    int r = j * HH + nb * 16 + half * 8 + g;
    int k = tile * 32 + kstep * 16 + khalf * 8 + 2 * th;
    float lo, hi;
    if (k < Kpad) {
        lo = (k < Kin)     ? Wih[(size_t)r * Kin + k] : 0.f;
        hi = (k + 1 < Kin) ? Wih[(size_t)r * Kin + k + 1] : 0.f;
    } else {
        lo = Whh[(size_t)r * HH + (k - Kpad)];
        hi = Whh[(size_t)r * HH + (k - Kpad) + 1];
    }
    dst[e] = pack_h2(lo, hi);
}

// High-occupancy image build: weights/x/bias/state-zero/counters. One launch.
__global__ void prep_all(const float* __restrict__ embed,
                         const int* __restrict__ questions,
                         const float* __restrict__ Wih1, const float* __restrict__ Whh1,
                         const float* __restrict__ bih1, const float* __restrict__ bhh1,
                         const float* __restrict__ Wih2, const float* __restrict__ Whh2,
                         const float* __restrict__ bih2, const float* __restrict__ bhh2)
{
    int blk = blockIdx.x;
    int tid = threadIdx.x;
    if (blk < PW1) {
        w_img_word(g_w1img, blk * 256 + tid, Wih1, Whh1, EE, E_PAD, NT1);
    } else if (blk < PW2) {
        w_img_word(g_w2img, (blk - PW1) * 256 + tid, Wih2, Whh2, HH, HH, NT2);
    } else if (blk < PX) {
        int e = (blk - PW2) * 256 + tid;      // < 32*12*1024
        int d = e & 1023;
        int ttile = e >> 10;
        int tile = ttile % NTILE0_1;
        int t = ttile / NTILE0_1;
        int half = d >> 9;
        int kstep = (d >> 8) & 1;
        int l = (d >> 3) & 31;
        int idx8 = (d & 7) ^ (l & 4);
        int mb = idx8 >> 2, khalf = (idx8 >> 1) & 1, rsel = idx8 & 1;
        int g = l >> 2, th = l & 3;
        int b = 32 * half + 16 * mb + 8 * rsel + g;
        int k = tile * 32 + kstep * 16 + khalf * 8 + 2 * th;
        int row = questions[b * TT + t];
        float lo = (k < EE)     ? embed[(size_t)row * EE + k] : 0.f;
        float hi = (k + 1 < EE) ? embed[(size_t)row * EE + k + 1] : 0.f;
        g_ximg[e] = pack_h2(lo, hi);
    } else if (blk < PBI) {
        int i = (blk - PX) * 256 + tid;       // < 4096
        g_bc1[i] = bih1[i] + bhh1[i];
        g_bc2[i] = bih2[i] + bhh2[i];
    } else if (blk < PZ) {
        int i = (blk - PBI) * 256 + tid;      // < 4*65536 + 2*32768
        if (i < 262144) {
            int sec = i >> 16, off = i & 65535;
            if      (sec == 0) g_h1[0][off] = 0.f;
            else if (sec == 1) g_h2[0][off] = 0.f;
            else if (sec == 2) g_c1[off] = 0.f;
            else               g_c2[off] = 0.f;
        } else {
            int j = i - 262144;
            if (j < 32768) g_h1img[0][j] = 0u;
            else           g_h2img[0][j - 32768] = 0u;
        }
    } else {
        if (tid < TT) { g_cnt1[tid] = 0u; g_cnt2[tid] = 0u; }
    }
}

// Persistent merged LSTM: 128 co-resident CTAs (1/SM).
// Blocks [0,64) = L2-role, [64,128) = L1-role; nb = blockIdx & 63.
//   L1 phase t waits cnt1[t-1]=64 and cnt2[t-2]=64 (ping-pong back-pressure).
//   L2 phase t waits cnt1[t]=64 and cnt2[t-1]=64.
// W images / x images are epoch-independent -> prefetched DURING the epoch
// spin; only h-image (A) loads are gated. 6-pair cp.async ring per half-block,
// named barriers, fragment-packed fp16 images, m16n8k16 f32-accum MMA,
// 4-way k-partials reduced through ring smem, thread-local LSTM epilogue.
__global__ __launch_bounds__(NTHREADS, 1) void lstm_persist(
    const int* __restrict__ qlen)
{
    extern __shared__ __align__(16) float sm[];
    const int tid   = threadIdx.x;
    const int lane  = tid & 31;
    const int warp  = tid >> 5;
    const int half  = warp >> 3;      // 0 or 1
    const int w8    = warp & 7;
    const int h_tid = tid & 255;

    const bool isL2 = blockIdx.x < NBLK;
    const int nb = blockIdx.x & (NBLK - 1);

    const int NT     = isL2 ? NT2 : NT1;
    const int ntile0 = isL2 ? NTILE0_2 : NTILE0_1;
    const int nsteps = NT >> 2;          // 11 or 16
    const unsigned* Wb = (isL2 ? g_w2img : g_w1img)
                       + (size_t)nb * NT * IMG_TILE_WORDS;
    const float* bc  = isL2 ? g_bc2 : g_bc1;
    float* cb        = isL2 ? g_c2 : g_c1;

    const unsigned smb = (unsigned)__cvta_generic_to_shared(sm)
                       + (unsigned)(half * HALF_RING_BYTES);

    const int wk2 = w8 & 1;
    const int wm  = (w8 >> 1) & 1;
    const int wn  = (w8 >> 2) & 1;
    const int g   = lane >> 2;
    const int th  = lane & 3;
    const unsigned lbase = (unsigned)(lane * 32) + ((lane & 4) ? 16u : 0u);
    const int barid = half + 1;
    const int kslot = half * 2 + wk2;

    // constant part of the h-image scatter address
    const int scat_base = (nb >> 1) * 1024 + wm * 512 + (nb & 1) * 256 + lane * 8;

    for (int t = 0; t < TT; ++t) {
        // ---- per-phase pointers (computable before the epoch wait) ----
        const unsigned *A0img, *A1img;
        const float *hprev;
        float *ho;
        unsigned *hoimg;
        if (isL2) {
            A0img = g_h1img[(t + 1) & 1];
            A1img = g_h2img[t & 1];
            hprev = g_h2[t & 1];
            ho    = g_h2[(t + 1) & 1];
            hoimg = g_h2img[(t + 1) & 1];
        } else {
            A0img = g_ximg + (size_t)t * (NTILE0_1 * IMG_TILE_WORDS);
            A1img = g_h1img[t & 1];
            hprev = g_h1[t & 1];
            ho    = g_h1[(t + 1) & 1];
            hoimg = g_h1img[(t + 1) & 1];
        }

        auto issue_W = [&](int s) {
            int st = (s % 6) * 2;
            int tb = 4 * s + 2 * half;
#pragma unroll
            for (int q = 0; q < 2; ++q) {
                const unsigned* wsrc = Wb + (size_t)(tb + q) * IMG_TILE_WORDS;
                unsigned ab = smb + (unsigned)((st + q) * STAGE_BYTES);
                cp16(ab + 4096u + (unsigned)(h_tid * 16), (const uint4*)wsrc + h_tid);
            }
        };
        auto issue_A = [&](int s) {
            int st = (s % 6) * 2;
            int tb = 4 * s + 2 * half;
#pragma unroll
            for (int q = 0; q < 2; ++q) {
                int tt = tb + q;
                const unsigned* asrc = (tt < ntile0)
                    ? A0img + (size_t)tt * IMG_TILE_WORDS
                    : A1img + (size_t)(tt - ntile0) * IMG_TILE_WORDS;
                unsigned ab = smb + (unsigned)((st + q) * STAGE_BYTES);
                cp16(ab + (unsigned)(h_tid * 16), (const uint4*)asrc + h_tid);
            }
        };

        // ---- prefetch epoch-independent tiles, then epoch wait ----
        issue_W(0); issue_W(1); issue_W(2); issue_W(3); issue_W(4);
        if (!isL2) { issue_A(0); issue_A(1); issue_A(2); }  // x tiles: all < ntile0

        if (tid == 0) {
            if (isL2) {
                while (ld_acq(&g_cnt1[t]) < NBLK) __nanosleep(40);
                if (t > 0) while (ld_acq(&g_cnt2[t - 1]) < NBLK) __nanosleep(40);
            } else {
                if (t > 0)  while (ld_acq(&g_cnt1[t - 1]) < NBLK) __nanosleep(40);
                if (t >= 2) while (ld_acq(&g_cnt2[t - 2]) < NBLK) __nanosleep(40);
            }
        }
        __syncthreads();

        // ---- commit prologue groups (A parts now unblocked) ----
        if (isL2) issue_A(0);
        asm volatile("cp.async.commit_group;");
        if (isL2) issue_A(1);
        asm volatile("cp.async.commit_group;");
        if (isL2) issue_A(2);
        asm volatile("cp.async.commit_group;");
        issue_A(3);
        asm volatile("cp.async.commit_group;");
        issue_A(4);
        asm volatile("cp.async.commit_group;");

        float acc[32];
#pragma unroll
        for (int i = 0; i < 32; ++i) acc[i] = 0.f;

        for (int s = 0; s < nsteps; ++s) {
            asm volatile("cp.async.wait_group 4;");
            asm volatile("bar.sync %0, 256;" :: "r"(barid));
            if (s + 5 < nsteps) { issue_A(s + 5); issue_W(s + 5); }
            asm volatile("cp.async.commit_group;");

            const unsigned st = smb + (unsigned)(((s % 6) * 2 + wk2) * STAGE_BYTES);
            const unsigned Ab  = st + (unsigned)(wm * 2048) + lbase;
            const unsigned Wsb = st + 4096u + (unsigned)(wn * 2048) + lbase;

#pragma unroll
            for (int c = 0; c < 2; ++c) {      // kstep of 16
                unsigned x0,x1,x2,x3,x4,x5,x6,x7;   // A logical idx8 0..7
                unsigned w0,w1,w2,w3,w4,w5,w6,w7;   // W logical idx8 0..7
                unsigned aaddr = Ab + (unsigned)(c * 1024);
                LDS128(x0, x1, x2, x3, aaddr);
                LDS128(x4, x5, x6, x7, aaddr ^ 16u);
                unsigned waddr = Wsb + (unsigned)(c * 1024);
                LDS128(w0, w1, w2, w3, waddr);
                LDS128(w4, w5, w6, w7, waddr ^ 16u);

#define MMAH(accp, A0_, A1_, A2_, A3_, B0_, B1_) \
    asm volatile("mma.sync.aligned.m16n8k16.row.col.f32.f16.f16.f32 " \
        "{%0,%1,%2,%3}, {%4,%5,%6,%7}, {%8,%9}, {%0,%1,%2,%3};" \
        : "+f"((accp)[0]), "+f"((accp)[1]), "+f"((accp)[2]), "+f"((accp)[3]) \
        : "r"(A0_), "r"(A1_), "r"(A2_), "r"(A3_), "r"(B0_), "r"(B1_))

                MMAH(&acc[0*8 + 0], x0, x1, x2, x3, w0, w1);  // j0 mb0
                MMAH(&acc[1*8 + 0], x0, x1, x2, x3, w2, w3);  // j1 mb0
                MMAH(&acc[2*8 + 0], x0, x1, x2, x3, w4, w5);  // j2 mb0
                MMAH(&acc[3*8 + 0], x0, x1, x2, x3, w6, w7);  // j3 mb0
                MMAH(&acc[0*8 + 4], x4, x5, x6, x7, w0, w1);  // j0 mb1
                MMAH(&acc[1*8 + 4], x4, x5, x6, x7, w2, w3);
                MMAH(&acc[2*8 + 4], x4, x5, x6, x7, w4, w5);
                MMAH(&acc[3*8 + 4], x4, x5, x6, x7, w6, w7);
#undef MMAH
            }
        }

        // ---- drain both half-rings, 4-way k-reduce via smem reuse ----
        asm volatile("cp.async.wait_group 0;");
        __syncthreads();

        if (kslot != 0) {
            int slot = (kslot - 1) * 4 + wm * 2 + wn;   // 0..11
            float4* dst = (float4*)(sm + slot * 1152 + lane * 36);
#pragma unroll
            for (int i = 0; i < 8; ++i)
                dst[i] = make_float4(acc[4*i], acc[4*i+1], acc[4*i+2], acc[4*i+3]);
        }
        __syncthreads();

        if (kslot == 0) {
#pragma unroll
            for (int kk = 1; kk < 4; ++kk) {
                const float4* src = (const float4*)(sm + ((kk - 1) * 4 + wm * 2 + wn) * 1152 + lane * 36);
#pragma unroll
                for (int i = 0; i < 8; ++i) {
                    float4 v = src[i];
                    acc[4*i]   += v.x; acc[4*i+1] += v.y;
                    acc[4*i+2] += v.z; acc[4*i+3] += v.w;
                }
            }

            // ---- thread-local LSTM epilogue ----
            // acc[j*8 + mb*4 + rsel*2 + e]:
            //   b = wm*32 + mb*16 + rsel*8 + g, u = nb*16 + wn*8 + 2*th + e
#pragma unroll
            for (int mb = 0; mb < 2; ++mb)
#pragma unroll
                for (int rsel = 0; rsel < 2; ++rsel) {
                    int b = wm * 32 + mb * 16 + rsel * 8 + g;
                    bool active = (t < qlen[b]);
                    float hw2[2];
#pragma unroll
                    for (int e = 0; e < 2; ++e) {
                        int u = nb * 16 + wn * 8 + 2 * th + e;
                        int ai = mb * 4 + rsel * 2 + e;
                        float gi = acc[0*8 + ai] + bc[u];
                        float gf = acc[1*8 + ai] + bc[u + HH];
                        float gg = acc[2*8 + ai] + bc[u + 2*HH];
                        float go = acc[3*8 + ai] + bc[u + 3*HH];
                        int idx = b * HH + u;
                        float c_old = cb[idx];
                        float h_old = hprev[idx];
                        float si = sigm_f(gi);
                        float sf = sigm_f(gf);
                        float so = sigm_f(go);
                        float tg = tanh_f(gg);
                        float cn = sf * c_old + si * tg;
                        float hn = so * tanh_f(cn);
                        float cw = active ? cn : c_old;
                        float hw = active ? hn : h_old;
                        cb[idx] = cw;
                        ho[idx] = hw;
                        hw2[e] = hw;
                    }
                    // one fp16x2 word into next-step A-image
                    int phys = (mb * 4 + wn * 2 + rsel) ^ (lane & 4);
                    hoimg[scat_base + phys] = pack_h2(hw2[0], hw2[1]);
                }
            __threadfence();   // publish h/c before epoch arrive
        }
        __syncthreads();       // all warps past reduction-smem reads

        if (tid == 0) {
            __threadfence();
            atomicAdd(isL2 ? &g_cnt2[t] : &g_cnt1[t], 1u);
        }
    }
}

// Output: E_q [B,1024,28,28] = tiled h2 (one WARP per (b,h) cell: broadcast
// value, ~6 coalesced float4 streaming stores/lane), then h1,h2,c1,c2 [B,1,H].
#define WO_EQ_BLOCKS 8192             // 8192 blocks x 8 warps = 65536 = B*H
#define WO_ST_BLOCKS 256              // 65536 float4s of state sections
__global__ void write_output_kernel(
    float* __restrict__ out,
    const float* __restrict__ h1,
    const float* __restrict__ h2,
    const float* __restrict__ c1,
    const float* __restrict__ c2)
{
    const unsigned n0q = (unsigned)BB * HH * 784u / 4u;   // 12,845,056 float4s
    float4* out4 = (float4*)out;
    if (blockIdx.x < WO_EQ_BLOCKS) {
        int bh   = blockIdx.x * 8 + (threadIdx.x >> 5);   // 0..65535
        int lane = threadIdx.x & 31;
        float v = h2[bh];
        float4 vv = make_float4(v, v, v, v);
        float4* dst = out4 + (size_t)bh * 196u;
#pragma unroll
        for (int i = 0; i < 7; ++i) {
            int x = lane + i * 32;
            if (x < 196) __stcs(dst + x, vv);
        }
    } else {
        unsigned idx = (blockIdx.x - WO_EQ_BLOCKS) * 256 + threadIdx.x; // < 65536
        unsigned sec = idx >> 14, off = idx & 16383;
        const float* src = (sec == 0) ? h1 : (sec == 1) ? h2 : (sec == 2) ? c1 : c2;
        __stcs(out4 + n0q + idx, ((const float4*)src)[off]);
    }
}

extern "C" void kernel_launch(void* const* d_in, const int* in_sizes, int n_in,
                              void* d_out, int out_size) {
    const int*   questions = (const int*)d_in[0];
    const int*   qlen      = (const int*)d_in[1];
    const float* embed     = (const float*)d_in[2];
    const float* Wih1      = (const float*)d_in[3];
    const float* Whh1      = (const float*)d_in[4];
    const float* bih1      = (const float*)d_in[5];
    const float* bhh1      = (const float*)d_in[6];
    const float* Wih2      = (const float*)d_in[7];
    const float* Whh2      = (const float*)d_in[8];
    const float* bih2      = (const float*)d_in[9];
    const float* bhh2      = (const float*)d_in[10];

    void* p;
    cudaGetSymbolAddress(&p, g_h1); float (*h1b)[BB*HH] = (float(*)[BB*HH])p;
    cudaGetSymbolAddress(&p, g_h2); float (*h2b)[BB*HH] = (float(*)[BB*HH])p;
    cudaGetSymbolAddress(&p, g_c1); float* c1p = (float*)p;
    cudaGetSymbolAddress(&p, g_c2); float* c2p = (float*)p;

    cudaFuncSetAttribute(lstm_persist,
                         cudaFuncAttributeMaxDynamicSharedMemorySize, SMEM_DYN);

    // high-occupancy image build (also zeroes epoch counters each replay)
    prep_all<<<PEND, 256>>>(embed, questions, Wih1, Whh1, bih1, bhh1,
                            Wih2, Whh2, bih2, bhh2);

    // one persistent kernel runs all 64 layer-steps with internal barriers
    lstm_persist<<<NCTAS, NTHREADS, SMEM_DYN>>>(qlen);

    // final states live in buffer index (T % 2) == 0
    write_output_kernel<<<WO_EQ_BLOCKS + WO_ST_BLOCKS, 256>>>(
        (float*)d_out, h1b[0], h2b[0], c1p, c2p);
}